// round 4
// baseline (speedup 1.0000x reference)
#include <cuda_runtime.h>
#include <cstdint>

#define BB 16
#define CC 16
#define HH 256
#define WW 256
#define TW 32
#define TH 8

// Scratch: new alpha channel (B*H*W floats = 4 MB)
__device__ float g_alpha[BB * HH * WW];

// Dynamic smem layout (floats):
//   s_state : CC*(TH+2)*(TW+2) = 5440
//   s_w1    : 128*48 = 6144
//   s_w2t   : 128*16 = 2048   (transposed [o][p])
//   s_b1    : 128
//   s_cw    : 432
//   s_b2    : 16
#define N_STATE (CC * (TH + 2) * (TW + 2))
#define N_W1 (128 * 48)
#define N_W2T (128 * 16)
#define SMEM_FLOATS (N_STATE + N_W1 + N_W2T + 128 + 432 + 16)

// ---- packed f32x2 helpers (sm_103a FFMA2/FADD2 path; ptxas never emits) ----
__device__ __forceinline__ uint64_t pk2(float lo, float hi) {
  uint64_t r;
  asm("mov.b64 %0, {%1, %2};" : "=l"(r) : "f"(lo), "f"(hi));
  return r;
}
__device__ __forceinline__ void upk2(float& lo, float& hi, uint64_t v) {
  asm("mov.b64 {%0, %1}, %2;" : "=f"(lo), "=f"(hi) : "l"(v));
}
__device__ __forceinline__ uint64_t ffma2(uint64_t a, uint64_t b, uint64_t c) {
  uint64_t d;
  asm("fma.rn.f32x2 %0, %1, %2, %3;" : "=l"(d) : "l"(a), "l"(b), "l"(c));
  return d;
}
__device__ __forceinline__ uint64_t fadd2(uint64_t a, uint64_t b) {
  uint64_t d;
  asm("add.rn.f32x2 %0, %1, %2;" : "=l"(d) : "l"(a), "l"(b));
  return d;
}

__global__ __launch_bounds__(256) void nca_pass1(
    const float* __restrict__ state, const float* __restrict__ rand_u,
    const float* __restrict__ conv_w, const float* __restrict__ w1,
    const float* __restrict__ b1, const float* __restrict__ w2,
    const float* __restrict__ b2, float* __restrict__ out) {
  extern __shared__ float smem[];
  float* s_state = smem;                 // [c][10][34]
  float* s_w1 = s_state + N_STATE;       // [o][48]
  float* s_w2t = s_w1 + N_W1;            // [o][16]
  float* s_b1 = s_w2t + N_W2T;           // [128]
  float* s_cw = s_b1 + 128;              // [48][9]
  float* s_b2 = s_cw + 432;              // [16]

  const int b = blockIdx.z;
  const int h0 = blockIdx.y * TH;
  const int w0 = blockIdx.x * TW;
  const int tid = threadIdx.x;
  const int tx = tid & 31;
  const int ty = tid >> 5;

  // Stage weights
  for (int i = tid; i < N_W1; i += 256) s_w1[i] = w1[i];
  for (int i = tid; i < N_W2T; i += 256) {
    int o = i >> 4, p = i & 15;
    s_w2t[i] = w2[p * 128 + o];
  }
  if (tid < 128) s_b1[tid] = b1[tid];
  if (tid < 16) s_b2[tid] = b2[tid];
  for (int i = tid; i < 432; i += 256) s_cw[i] = conv_w[i];

  // Stage state tile with halo (zero pad)
  for (int i = tid; i < N_STATE; i += 256) {
    int c = i / 340;
    int r = i - c * 340;
    int hh = r / 34;
    int ww = r - hh * 34;
    int gh = h0 + hh - 1;
    int gw = w0 + ww - 1;
    float v = 0.0f;
    if (gh >= 0 && gh < HH && gw >= 0 && gw < WW)
      v = state[((b * CC + c) * HH + gh) * WW + gw];
    s_state[i] = v;
  }
  __syncthreads();

  // Depthwise conv -> perc[48] (scalar; 2.4% of FLOPs)
  float perc[48];
#pragma unroll
  for (int c = 0; c < CC; c++) {
    float v[9];
#pragma unroll
    for (int dy = 0; dy < 3; dy++)
#pragma unroll
      for (int dx = 0; dx < 3; dx++)
        v[dy * 3 + dx] = s_state[c * 340 + (ty + dy) * 34 + (tx + dx)];
#pragma unroll
    for (int k = 0; k < 3; k++) {
      const float* f = &s_cw[(3 * c + k) * 9];
      float acc = 0.0f;
#pragma unroll
      for (int t = 0; t < 9; t++) acc = fmaf(f[t], v[t], acc);
      perc[3 * c + k] = acc;
    }
  }

  // Pack perc into 24 f32x2 lanes
  uint64_t perc2[24];
#pragma unroll
  for (int j = 0; j < 24; j++) perc2[j] = pk2(perc[2 * j], perc[2 * j + 1]);

  // ds accumulators as 8 f32x2 lanes, seeded with b2
  uint64_t ds2[8];
#pragma unroll
  for (int p = 0; p < 8; p++) ds2[p] = pk2(s_b2[2 * p], s_b2[2 * p + 1]);

  // Fused MLP: 48 -> 128 (relu) -> 16, streaming over hidden units (FFMA2)
#pragma unroll 2
  for (int o = 0; o < 128; o++) {
    const uint64_t* wr = (const uint64_t*)(s_w1 + o * 48);  // 24 packed pairs
    uint64_t accA = 0ull, accB = 0ull;                       // {0.f,0.f} lanes
#pragma unroll
    for (int j = 0; j < 24; j += 2) {
      accA = ffma2(wr[j], perc2[j], accA);
      accB = ffma2(wr[j + 1], perc2[j + 1], accB);
    }
    // packed merge, then one unpack + one scalar add
    uint64_t accM = fadd2(accA, accB);
    float m0, m1;
    upk2(m0, m1, accM);
    float hs = fmaxf(s_b1[o] + (m0 + m1), 0.0f);

    uint64_t hh2 = pk2(hs, hs);
    const uint64_t* w2r = (const uint64_t*)(s_w2t + o * 16);  // 8 packed pairs
#pragma unroll
    for (int p = 0; p < 8; p++) ds2[p] = ffma2(w2r[p], hh2, ds2[p]);
  }

  float ds[16];
#pragma unroll
  for (int p = 0; p < 8; p++) upk2(ds[2 * p], ds[2 * p + 1], ds2[p]);

  // Stochastic update + write new_state; stash new alpha
  const int gh = h0 + ty;
  const int gw = w0 + tx;
#pragma unroll
  for (int c = 0; c < CC; c++) {
    int idx = ((b * CC + c) * HH + gh) * WW + gw;
    float st = s_state[c * 340 + (ty + 1) * 34 + (tx + 1)];
    float m = (rand_u[idx] < 0.5f) ? 1.0f : 0.0f;
    float ns = fmaf(ds[c], m, st);
    out[idx] = ns;
    if (c == 3) g_alpha[(b * HH + gh) * WW + gw] = ns;
  }
}

// Pass 2: alive mask (3x3 maxpool of new alpha, -inf padding) -> zero dead pixels
__global__ __launch_bounds__(256) void nca_pass2(float* __restrict__ out) {
  int t = blockIdx.x * 256 + threadIdx.x;
  if (t >= BB * HH * WW) return;
  int b = t / (HH * WW);
  int r = t - b * (HH * WW);
  int h = r / WW;
  int w = r - h * WW;

  float m = -3.402823466e38f;
#pragma unroll
  for (int dy = -1; dy <= 1; dy++) {
    int hh = h + dy;
    if (hh < 0 || hh >= HH) continue;
#pragma unroll
    for (int dx = -1; dx <= 1; dx++) {
      int ww = w + dx;
      if (ww < 0 || ww >= WW) continue;
      float v = g_alpha[(b * HH + hh) * WW + ww];
      m = fmaxf(m, v);
    }
  }
  if (!(m > 0.1f)) {
#pragma unroll
    for (int c = 0; c < CC; c++) out[((b * CC + c) * HH + h) * WW + w] = 0.0f;
  }
}

extern "C" void kernel_launch(void* const* d_in, const int* in_sizes, int n_in,
                              void* d_out, int out_size) {
  const float* state = (const float*)d_in[0];
  const float* rand_u = (const float*)d_in[1];
  const float* conv_w = (const float*)d_in[2];
  const float* w1 = (const float*)d_in[3];
  const float* b1 = (const float*)d_in[4];
  const float* w2 = (const float*)d_in[5];
  const float* b2 = (const float*)d_in[6];
  float* out = (float*)d_out;

  const int smem_bytes = SMEM_FLOATS * (int)sizeof(float);
  cudaFuncSetAttribute(nca_pass1, cudaFuncAttributeMaxDynamicSharedMemorySize,
                       smem_bytes);

  dim3 grid(WW / TW, HH / TH, BB);
  nca_pass1<<<grid, 256, smem_bytes>>>(state, rand_u, conv_w, w1, b1, w2, b2,
                                       out);

  int npix = BB * HH * WW;
  nca_pass2<<<(npix + 255) / 256, 256>>>(out);
}